// round 1
// baseline (speedup 1.0000x reference)
#include <cuda_runtime.h>
#include <cstddef>

// ResidualVectorQuantizer: N x D points, L layers of NE codes each (D=32, NE=256, L=4).
// Outputs (flattened into d_out, float32): x_q [N*D], mean_loss [1], indices [N*L].

#define RVQ_D   32
#define RVQ_NE  256
#define RVQ_L   4
#define TPB     128
#define RVQ_BETA 0.25f
#define MAXBLK  8192

// Device scratch (no allocations allowed).
__device__ float g_cnorm[RVQ_L * RVQ_NE];
__device__ float g_partial[MAXBLK * RVQ_L];

typedef unsigned long long u64;

__device__ __forceinline__ u64 fma2(u64 a, u64 b, u64 c) {
    u64 d;
    asm("fma.rn.f32x2 %0, %1, %2, %3;" : "=l"(d) : "l"(a), "l"(b), "l"(c));
    return d;
}
__device__ __forceinline__ u64 add2(u64 a, u64 b) {
    u64 d;
    asm("add.rn.f32x2 %0, %1, %2;" : "=l"(d) : "l"(a), "l"(b));
    return d;
}
__device__ __forceinline__ float2 unpk(u64 v) {
    float2 f;
    asm("mov.b64 {%0, %1}, %2;" : "=f"(f.x), "=f"(f.y) : "l"(v));
    return f;
}
__device__ __forceinline__ u64 pk(float x, float y) {
    u64 v;
    asm("mov.b64 %0, {%1, %2};" : "=l"(v) : "f"(x), "f"(y));
    return v;
}

// Precompute per-code squared norms (tiny, runs once per launch).
__global__ void rvq_norm_kernel(const float* __restrict__ cb) {
    int e = blockIdx.x * blockDim.x + threadIdx.x;
    if (e < RVQ_L * RVQ_NE) {
        const float* r = cb + (size_t)e * RVQ_D;
        float s = 0.f;
        #pragma unroll
        for (int k = 0; k < RVQ_D; k++) s = fmaf(r[k], r[k], s);
        g_cnorm[e] = s;
    }
}

__global__ void __launch_bounds__(TPB, 5) rvq_main_kernel(
    const float* __restrict__ x, const float* __restrict__ cb,
    float* __restrict__ out, int N, int has_loss, int has_idx)
{
    __shared__ __align__(16) float scb[RVQ_NE * RVQ_D];  // one layer's codebook: 32KB
    __shared__ float scn[RVQ_NE];
    __shared__ float red[TPB];

    const int tid = threadIdx.x;
    const int p = blockIdx.x * TPB + tid;
    const bool active = (p < N);

    // Residual held as 16 packed f32x2 values.
    u64 r2[RVQ_D / 2];
    if (active) {
        const ulonglong2* xr = (const ulonglong2*)(x + (size_t)p * RVQ_D);
        #pragma unroll
        for (int j = 0; j < RVQ_D / 4; j++) {
            ulonglong2 v = xr[j];
            r2[2*j]   = v.x;
            r2[2*j+1] = v.y;
        }
    }

    float tloss[RVQ_L];
    int bidx[RVQ_L];
    #pragma unroll
    for (int l = 0; l < RVQ_L; l++) { tloss[l] = 0.f; bidx[l] = 0; }

    for (int l = 0; l < RVQ_L; l++) {
        __syncthreads();  // previous layer's scb reads complete before restage
        // Stage this layer's codebook into shared (coalesced, conflict-free).
        {
            const float4* src = (const float4*)(cb + (size_t)l * RVQ_NE * RVQ_D);
            float4* dst = (float4*)scb;
            #pragma unroll
            for (int i = tid; i < RVQ_NE * RVQ_D / 4; i += TPB) dst[i] = src[i];
            for (int i = tid; i < RVQ_NE; i += TPB) scn[i] = g_cnorm[l * RVQ_NE + i];
        }
        __syncthreads();

        if (active) {
            float best = 3.402823466e38f;
            int bi = 0;
            const ulonglong2* cbv = (const ulonglong2*)scb;
            #pragma unroll 2
            for (int e = 0; e < RVQ_NE; e++) {
                const ulonglong2* cp = cbv + e * (RVQ_D / 4);
                u64 a0 = 0ULL, a1 = 0ULL, a2 = 0ULL, a3 = 0ULL;
                #pragma unroll
                for (int j = 0; j < RVQ_D / 4; j += 2) {
                    ulonglong2 ca = cp[j];
                    ulonglong2 cbq = cp[j + 1];
                    a0 = fma2(r2[2*j],     ca.x,  a0);
                    a1 = fma2(r2[2*j + 1], ca.y,  a1);
                    a2 = fma2(r2[2*j + 2], cbq.x, a2);
                    a3 = fma2(r2[2*j + 3], cbq.y, a3);
                }
                u64 s = add2(add2(a0, a1), add2(a2, a3));
                float2 sf = unpk(s);
                float dot = sf.x + sf.y;
                // d = ||r||^2 + ||c||^2 - 2 r.c ; drop the per-point constant ||r||^2.
                float score = fmaf(-2.0f, dot, scn[e]);
                if (score < best) { best = score; bi = e; }  // strict '<' keeps first index
            }
            bidx[l] = bi;

            // Epilogue: gather chosen code from GLOBAL (L2-resident) to dodge
            // the 32-way smem bank conflict of a row-stride-128B gather.
            const ulonglong2* cg = (const ulonglong2*)(cb + ((size_t)l * RVQ_NE + bi) * RVQ_D);
            float ls = 0.f;
            #pragma unroll
            for (int j = 0; j < RVQ_D / 4; j++) {
                ulonglong2 cv = cg[j];
                float2 c0 = unpk(cv.x), c1 = unpk(cv.y);
                float2 ra = unpk(r2[2*j]), rb = unpk(r2[2*j + 1]);
                float t, xres;
                // mimic reference: t = xq - r; xres = r + t; loss += t*t; r -= xres
                t = c0.x - ra.x; ls = fmaf(t, t, ls); xres = ra.x + t; ra.x = ra.x - xres;
                t = c0.y - ra.y; ls = fmaf(t, t, ls); xres = ra.y + t; ra.y = ra.y - xres;
                t = c1.x - rb.x; ls = fmaf(t, t, ls); xres = rb.x + t; rb.x = rb.x - xres;
                t = c1.y - rb.y; ls = fmaf(t, t, ls); xres = rb.y + t; rb.y = rb.y - xres;
                r2[2*j]     = pk(ra.x, ra.y);
                r2[2*j + 1] = pk(rb.x, rb.y);
            }
            tloss[l] = ls;
        }
    }

    // Deterministic per-block loss reduction (tree), one partial per (block, layer).
    #pragma unroll
    for (int l = 0; l < RVQ_L; l++) {
        __syncthreads();
        red[tid] = tloss[l];
        __syncthreads();
        #pragma unroll
        for (int s = TPB / 2; s > 0; s >>= 1) {
            if (tid < s) red[tid] += red[tid + s];
            __syncthreads();
        }
        if (tid == 0) g_partial[(size_t)blockIdx.x * RVQ_L + l] = red[0];
    }

    // Outputs: x_q = x - final residual (== sum of x_res up to 1 ulp), indices.
    if (active) {
        const ulonglong2* xr = (const ulonglong2*)(x + (size_t)p * RVQ_D);
        ulonglong2* qo = (ulonglong2*)(out + (size_t)p * RVQ_D);
        #pragma unroll
        for (int j = 0; j < RVQ_D / 4; j++) {
            ulonglong2 xv = xr[j];
            float2 x0 = unpk(xv.x), x1 = unpk(xv.y);
            float2 r0 = unpk(r2[2*j]), r1 = unpk(r2[2*j + 1]);
            ulonglong2 q;
            q.x = pk(x0.x - r0.x, x0.y - r0.y);
            q.y = pk(x1.x - r1.x, x1.y - r1.y);
            qo[j] = q;
        }
        if (has_idx) {
            float* oi = out + (size_t)N * RVQ_D + (has_loss ? 1 : 0) + (size_t)p * RVQ_L;
            #pragma unroll
            for (int l = 0; l < RVQ_L; l++) oi[l] = (float)bidx[l];
        }
    }
}

// Final fixed-order (deterministic) loss accumulation across blocks.
__global__ void rvq_loss_kernel(float* __restrict__ out, int N, int nblk) {
    __shared__ double sl[RVQ_L];
    int l = threadIdx.x;
    if (l < RVQ_L) {
        double s = 0.0;
        for (int b = 0; b < nblk; b++) s += (double)g_partial[(size_t)b * RVQ_L + l];
        sl[l] = s;
    }
    __syncthreads();
    if (threadIdx.x == 0) {
        double nd = (double)N * (double)RVQ_D;
        double ml = 0.0;
        #pragma unroll
        for (int l2 = 0; l2 < RVQ_L; l2++)
            ml += (1.0 + (double)RVQ_BETA) * (sl[l2] / nd);
        out[(size_t)N * RVQ_D] = (float)(ml / (double)RVQ_L);
    }
}

extern "C" void kernel_launch(void* const* d_in, const int* in_sizes, int n_in,
                              void* d_out, int out_size) {
    // Identify inputs by size: x is N*D (large), codebooks is L*NE*D (small).
    const float* x;
    const float* cb;
    int nx;
    if (n_in >= 2 && in_sizes[0] >= in_sizes[1]) {
        x = (const float*)d_in[0]; cb = (const float*)d_in[1]; nx = in_sizes[0];
    } else {
        x = (const float*)d_in[1]; cb = (const float*)d_in[0]; nx = in_sizes[1];
    }
    int N = nx / RVQ_D;
    float* out = (float*)d_out;

    long long need_full = (long long)N * RVQ_D + 1 + (long long)N * RVQ_L;
    int has_loss = (out_size > (long long)N * RVQ_D) ? 1 : 0;
    int has_idx  = (out_size >= need_full) ? 1 : 0;

    int nblk = (N + TPB - 1) / TPB;
    if (nblk > MAXBLK) nblk = MAXBLK;  // safety; N=131072 -> 1024 blocks

    int norm_blocks = (RVQ_L * RVQ_NE + 255) / 256;
    rvq_norm_kernel<<<norm_blocks, 256>>>(cb);
    rvq_main_kernel<<<nblk, TPB>>>(x, cb, out, N, has_loss, has_idx);
    if (has_loss) rvq_loss_kernel<<<1, 32>>>(out, N, nblk);
}

// round 3
// speedup vs baseline: 1.1541x; 1.1541x over previous
#include <cuda_runtime.h>
#include <cstdint>
#include <cstddef>

// ResidualVectorQuantizer via warp-level tf32 MMA (2-split exact-enough fp32 GEMM).
// N x D points, L layers of NE codes (D=32, NE=256, L=4).
// Out (float32): x_q [N*D], mean_loss [1], indices [N*L].
// NOTE: harness compiles at compute_100 (no 'a') -> tcgen05 unavailable; use mma.sync.

#define DD   32
#define NEC  256
#define LL   4
#define TM   128
#define RVQ_BETA 0.25f
#define MAXBLK_P 8192

// packed global B: per code 72 floats (288B): [h pairs 32 | l pairs 32 | cnh cnl 0 0 | pad 4]
__device__ float g_bp[LL * NEC * 72];
__device__ float g_part[MAXBLK_P * LL];
__device__ unsigned g_ctr;   // zero-init; reset by last block each run

// smem offsets (bytes)
#define OFF_A    0                    // 128 points * 288B = 36864
#define OFF_B    36864                // 128 codes  * 288B = 36864
#define OFF_ARG  73728                // 128 ints
#define OFF_RED  74240                // 128 doubles (also used as floats)
#define OFF_FLAG 75264
#define SMEM_BYTES 75392

__device__ __forceinline__ uint32_t tf32c(float v) {
    uint32_t r;
    asm("cvt.rna.tf32.f32 %0, %1;" : "=r"(r) : "f"(v));
    return r;
}
__device__ __forceinline__ void tsplit(float v, uint32_t& h, uint32_t& l) {
    h = tf32c(v);
    l = tf32c(v - __uint_as_float(h));
}

#define MMA8(C, A, b0v, b1v) \
    asm volatile("mma.sync.aligned.m16n8k8.row.col.f32.tf32.tf32.f32 " \
        "{%0,%1,%2,%3}, {%4,%5,%6,%7}, {%8,%9}, {%0,%1,%2,%3};" \
        : "+f"((C)[0]), "+f"((C)[1]), "+f"((C)[2]), "+f"((C)[3]) \
        : "r"((A)[0]), "r"((A)[1]), "r"((A)[2]), "r"((A)[3]), "r"(b0v), "r"(b1v))

// ---------------- prep: pack codebooks as tf32 splits + half-norm splits ----------------
__global__ void rvq_prep(const float* __restrict__ cb) {
    int e = blockIdx.x * blockDim.x + threadIdx.x;
    if (e >= LL * NEC) return;
    const float* row = cb + (size_t)e * DD;
    float* dst = g_bp + (size_t)e * 72;
    float h[DD], lo[DD];
    float cn = 0.f;
    #pragma unroll
    for (int k = 0; k < DD; k++) {
        float v = row[k];
        uint32_t hh, ll;
        tsplit(v, hh, ll);
        h[k] = __uint_as_float(hh);
        lo[k] = __uint_as_float(ll);
        cn = fmaf(v, v, cn);
    }
    cn *= 0.5f;
    #pragma unroll
    for (int ks = 0; ks < 4; ks++)
        #pragma unroll
        for (int kk = 0; kk < 4; kk++) {
            dst[ks * 8 + kk * 2]          = h[ks * 8 + kk];
            dst[ks * 8 + kk * 2 + 1]      = h[ks * 8 + kk + 4];
            dst[32 + ks * 8 + kk * 2]     = lo[ks * 8 + kk];
            dst[32 + ks * 8 + kk * 2 + 1] = lo[ks * 8 + kk + 4];
        }
    uint32_t ch, cl;
    tsplit(cn, ch, cl);
    dst[64] = __uint_as_float(ch);
    dst[65] = __uint_as_float(cl);
    #pragma unroll
    for (int k = 66; k < 72; k++) dst[k] = 0.f;
}

// ---------------- main ----------------
__global__ void __launch_bounds__(TM, 2) rvq_mma_kernel(
    const float* __restrict__ x, const float* __restrict__ cb,
    float* __restrict__ out, int N, int has_loss, int has_idx, int nblk)
{
    extern __shared__ char smem[];
    const int tid = threadIdx.x;
    const int w = tid >> 5;
    const int lane = tid & 31;
    const int q = lane >> 2;       // group (0..7): MMA row group
    const int kk = lane & 3;       // thread-in-group
    const int p = blockIdx.x * TM + tid;
    const bool active = (p < N);

    // residual in registers
    float r[DD];
    if (active) {
        const float4* xr = (const float4*)(x + (size_t)p * DD);
        #pragma unroll
        for (int j = 0; j < DD / 4; j++) {
            float4 v = xr[j];
            r[4*j] = v.x; r[4*j+1] = v.y; r[4*j+2] = v.z; r[4*j+3] = v.w;
        }
    } else {
        #pragma unroll
        for (int j = 0; j < DD; j++) r[j] = 0.f;
    }

    // constant A fragment for the cn k-step: A[m][0]=A[m][1]=1, rest 0
    uint32_t A1[4];
    A1[0] = (kk < 2) ? 0x3f800000u : 0u;
    A1[1] = A1[0];
    A1[2] = 0u; A1[3] = 0u;

    float tl[LL];
    int bia[LL];

    for (int l = 0; l < LL; l++) {
        __syncthreads();   // everyone done reading A_s/B_s from previous layer

        // ---- write negated residual splits into A_s (packed pairs) ----
        {
            char* ap = smem + OFF_A + tid * 288;
            #pragma unroll
            for (int ks = 0; ks < 4; ks++)
                #pragma unroll
                for (int c = 0; c < 4; c++) {
                    int k0 = ks * 8 + c;
                    uint32_t h0, l0, h1, l1;
                    tsplit(-r[k0], h0, l0);
                    tsplit(-r[k0 + 4], h1, l1);
                    *(uint2*)(ap + ks * 32 + c * 8)       = make_uint2(h0, h1);
                    *(uint2*)(ap + 128 + ks * 32 + c * 8) = make_uint2(l0, l1);
                }
        }
        // ---- stage B chunk 0 (linear copy; layouts match) ----
        {
            const float4* src = (const float4*)(g_bp + ((size_t)l * 256) * 72);
            float4* dst = (float4*)(smem + OFF_B);
            #pragma unroll 3
            for (int i = tid; i < 2304; i += TM) dst[i] = src[i];
        }
        __syncthreads();

        // ---- load A fragments (resident for the whole layer) ----
        uint32_t a[2][2][4][4];
        {
            const char* ab = smem + OFF_A + ((size_t)w * 32 + q) * 288 + kk * 8;
            #pragma unroll
            for (int m = 0; m < 2; m++)
                #pragma unroll
                for (int s = 0; s < 2; s++)
                    #pragma unroll
                    for (int ks = 0; ks < 4; ks++) {
                        uint2 p0 = *(const uint2*)(ab + (m * 16) * 288 + s * 128 + ks * 32);
                        uint2 p1 = *(const uint2*)(ab + (m * 16 + 8) * 288 + s * 128 + ks * 32);
                        a[m][s][ks][0] = p0.x;
                        a[m][s][ks][2] = p0.y;
                        a[m][s][ks][1] = p1.x;
                        a[m][s][ks][3] = p1.y;
                    }
        }

        float best[4];
        int bidx[4];
        #pragma unroll
        for (int j = 0; j < 4; j++) { best[j] = 3.402823466e38f; bidx[j] = 0; }

        for (int chunk = 0; chunk < 2; chunk++) {
            if (chunk == 1) {
                __syncthreads();   // done reading B chunk0
                const float4* src = (const float4*)(g_bp + ((size_t)l * 256 + 128) * 72);
                float4* dst = (float4*)(smem + OFF_B);
                #pragma unroll 3
                for (int i = tid; i < 2304; i += TM) dst[i] = src[i];
                __syncthreads();
            }

            const char* bb = smem + OFF_B + q * 288 + kk * 8;
            #pragma unroll 2
            for (int nt = 0; nt < 16; nt++) {
                const char* bp = bb + nt * (8 * 288);
                uint32_t bh[4][2], bl2[4][2];
                #pragma unroll
                for (int ks = 0; ks < 4; ks++) {
                    uint2 t = *(const uint2*)(bp + ks * 32);
                    bh[ks][0] = t.x; bh[ks][1] = t.y;
                    uint2 u = *(const uint2*)(bp + 128 + ks * 32);
                    bl2[ks][0] = u.x; bl2[ks][1] = u.y;
                }
                uint32_t bcn = *(const uint32_t*)(smem + OFF_B + (nt * 8 + q) * 288 + 256 + kk * 4);

                // two accumulator sets per M-tile -> 4 independent HMMA chains
                float Ca[2][4], Cb[2][4];
                #pragma unroll
                for (int m = 0; m < 2; m++)
                    #pragma unroll
                    for (int j = 0; j < 4; j++) { Ca[m][j] = 0.f; Cb[m][j] = 0.f; }

                #pragma unroll
                for (int m = 0; m < 2; m++) {
                    #pragma unroll
                    for (int ks = 0; ks < 4; ks++) MMA8(Ca[m], a[m][0][ks], bh[ks][0], bh[ks][1]);   // h*h
                    #pragma unroll
                    for (int ks = 0; ks < 4; ks++) MMA8(Cb[m], a[m][1][ks], bh[ks][0], bh[ks][1]);   // l*h
                    #pragma unroll
                    for (int ks = 0; ks < 4; ks++) MMA8(Cb[m], a[m][0][ks], bl2[ks][0], bl2[ks][1]); // h*l
                    MMA8(Ca[m], A1, bcn, 0u);                                                        // + cn/2
                }

                int nb = chunk * 128 + nt * 8 + kk * 2;
                #pragma unroll
                for (int m = 0; m < 2; m++)
                    #pragma unroll
                    for (int hi = 0; hi < 2; hi++)
                        #pragma unroll
                        for (int j = 0; j < 2; j++) {
                            float sc = Ca[m][hi * 2 + j] + Cb[m][hi * 2 + j];
                            int jj = m * 2 + hi;
                            int n = nb + j;
                            if (sc < best[jj]) { best[jj] = sc; bidx[jj] = n; }
                        }
            }
        }

        // ---- reduce argmin across the 4 lanes of each group (xor 1,2) ----
        #pragma unroll
        for (int jj = 0; jj < 4; jj++) {
            #pragma unroll
            for (int ofs = 1; ofs <= 2; ofs <<= 1) {
                float ob = __shfl_xor_sync(0xffffffffu, best[jj], ofs);
                int oi = __shfl_xor_sync(0xffffffffu, bidx[jj], ofs);
                if (ob < best[jj] || (ob == best[jj] && oi < bidx[jj])) {
                    best[jj] = ob; bidx[jj] = oi;
                }
            }
        }
        int* argb = (int*)(smem + OFF_ARG);
        if (kk == 0) {
            #pragma unroll
            for (int jj = 0; jj < 4; jj++)
                argb[w * 32 + q + (jj & 1) * 8 + (jj >> 1) * 16] = bidx[jj];
        }
        __syncwarp();
        int bi = argb[w * 32 + lane];
        bia[l] = bi;

        // ---- residual update + loss (exact fp op sequence of the reference) ----
        if (active) {
            const float4* cg = (const float4*)(cb + ((size_t)l * NEC + bi) * DD);
            float ls = 0.f;
            #pragma unroll
            for (int j = 0; j < DD / 4; j++) {
                float4 c = cg[j];
                float t0, xres;
                t0 = c.x - r[4*j];   ls = fmaf(t0, t0, ls); xres = r[4*j]   + t0; r[4*j]   = r[4*j]   - xres;
                t0 = c.y - r[4*j+1]; ls = fmaf(t0, t0, ls); xres = r[4*j+1] + t0; r[4*j+1] = r[4*j+1] - xres;
                t0 = c.z - r[4*j+2]; ls = fmaf(t0, t0, ls); xres = r[4*j+2] + t0; r[4*j+2] = r[4*j+2] - xres;
                t0 = c.w - r[4*j+3]; ls = fmaf(t0, t0, ls); xres = r[4*j+3] + t0; r[4*j+3] = r[4*j+3] - xres;
            }
            tl[l] = ls;
        } else {
            tl[l] = 0.f;
        }
    }

    // ---- outputs: x_q = x - r_final, indices ----
    if (active) {
        const float4* xr = (const float4*)(x + (size_t)p * DD);
        float4* qo = (float4*)(out + (size_t)p * DD);
        #pragma unroll
        for (int j = 0; j < DD / 4; j++) {
            float4 v = xr[j];
            float4 qv;
            qv.x = v.x - r[4*j];   qv.y = v.y - r[4*j+1];
            qv.z = v.z - r[4*j+2]; qv.w = v.w - r[4*j+3];
            qo[j] = qv;
        }
        if (has_idx) {
            float* oi = out + (size_t)N * DD + (has_loss ? 1 : 0) + (size_t)p * LL;
            #pragma unroll
            for (int l = 0; l < LL; l++) oi[l] = (float)bia[l];
        }
    }

    // ---- per-block loss partials (deterministic tree) ----
    {
        float* red = (float*)(smem + OFF_RED);
        #pragma unroll
        for (int l = 0; l < LL; l++) {
            __syncthreads();
            red[tid] = tl[l];
            __syncthreads();
            #pragma unroll
            for (int s = TM / 2; s > 0; s >>= 1) {
                if (tid < s) red[tid] += red[tid + s];
                __syncthreads();
            }
            if (tid == 0) g_part[(size_t)blockIdx.x * LL + l] = red[0];
        }
    }

    // ---- last block finalizes loss (deterministic fixed-order), resets ctr ----
    __threadfence();
    unsigned* flag = (unsigned*)(smem + OFF_FLAG);
    if (tid == 0) {
        unsigned done = atomicAdd(&g_ctr, 1u);
        *flag = (done == (unsigned)(nblk - 1)) ? 1u : 0u;
    }
    __syncthreads();
    if (*flag) {
        __threadfence();
        double acc = 0.0;
        for (int b = tid; b < nblk; b += TM) {
            #pragma unroll
            for (int l = 0; l < LL; l++) acc += (double)g_part[(size_t)b * LL + l];
        }
        double* dred = (double*)(smem + OFF_RED);
        dred[tid] = acc;
        __syncthreads();
        #pragma unroll
        for (int s = TM / 2; s > 0; s >>= 1) {
            if (tid < s) dred[tid] += dred[tid + s];
            __syncthreads();
        }
        if (tid == 0) {
            if (has_loss) {
                double wgt = (1.0 + (double)RVQ_BETA) / ((double)N * (double)DD * (double)LL);
                out[(size_t)N * DD] = (float)(dred[0] * wgt);
            }
            g_ctr = 0u;
        }
    }
}

extern "C" void kernel_launch(void* const* d_in, const int* in_sizes, int n_in,
                              void* d_out, int out_size) {
    const float* x;
    const float* cb;
    int nx;
    if (n_in >= 2 && in_sizes[0] >= in_sizes[1]) {
        x = (const float*)d_in[0]; cb = (const float*)d_in[1]; nx = in_sizes[0];
    } else {
        x = (const float*)d_in[1]; cb = (const float*)d_in[0]; nx = in_sizes[1];
    }
    int N = nx / DD;
    float* out = (float*)d_out;

    long long need_full = (long long)N * DD + 1 + (long long)N * LL;
    int has_loss = (out_size > (long long)N * DD) ? 1 : 0;
    int has_idx  = (out_size >= need_full) ? 1 : 0;

    int nblk = (N + TM - 1) / TM;
    if (nblk > MAXBLK_P) nblk = MAXBLK_P;

    cudaFuncSetAttribute(rvq_mma_kernel, cudaFuncAttributeMaxDynamicSharedMemorySize, SMEM_BYTES);

    rvq_prep<<<(LL * NEC + 127) / 128, 128>>>(cb);
    rvq_mma_kernel<<<nblk, TM, SMEM_BYTES>>>(x, cb, out, N, has_loss, has_idx, nblk);
}

// round 4
// speedup vs baseline: 2.5350x; 2.1965x over previous
#include <cuda_runtime.h>
#include <cuda_fp16.h>
#include <cstdint>
#include <cstddef>

// ResidualVectorQuantizer via warp-level fp16 MMA, 3-term exact-enough fp32 GEMM.
// N x D points, L layers of NE codes (D=32, NE=256, L=4).
// Out (float32): x_q [N*D], mean_loss [1], indices [N*L].
// Harness target is compute_100 (no 'a'): tcgen05 unavailable; mma.sync only.

#define DD   32
#define NEC  256
#define LL   4
#define TM   128
#define RVQ_BETA 0.25f
#define MAXBLK_P 8192

// ---- global scratch ----
// B pack: per code 32 words (128B): h half2 words [16] then l half2 words [16],
// kk-major: word[kk*4+t], t: (2kk,2kk+1),(2kk+8,2kk+9),(16+2kk,..),(24+2kk,..)
__device__ uint32_t g_bp[LL * NEC * 32];
__device__ float    g_cn[LL * NEC];          // 0.5*||c||^2 (fp32)
__device__ float    g_part[MAXBLK_P * LL];
__device__ unsigned g_ctr;                   // zero-init; reset by last block

// ---- smem map (bytes) ----
#define OFF_SH   0                     // shared A-then-B region
                                       //   A: 128 rows x 144B = 18432
                                       //   B: 128 codes x 192B = 24576
#define OFF_R    24576                 // residual: 128 x 144B = 18432
#define OFF_CN   43008                 // 4096 (all layers' cn)
#define OFF_ARG  47104                 // 512
#define OFF_RED  47616                 // 1024 (doubles/floats)
#define OFF_FLAG 48640
#define SMEM_BYTES 48768

__device__ __forceinline__ uint32_t packh2(__half a, __half b) {
    __half2 h = __halves2half2(a, b);
    return *(uint32_t*)&h;
}
// split v into h (fp16) + l (fp16 of remainder); h+l ~ v to ~2^-22 rel
__device__ __forceinline__ void sp16(float v, __half& h, __half& l) {
    h = __float2half_rn(v);
    l = __float2half_rn(v - __half2float(h));
}

#define MMA16(C, A0, A1, A2, A3, B0, B1) \
    asm volatile("mma.sync.aligned.m16n8k16.row.col.f32.f16.f16.f32 " \
        "{%0,%1,%2,%3}, {%4,%5,%6,%7}, {%8,%9}, {%0,%1,%2,%3};" \
        : "+f"((C)[0]), "+f"((C)[1]), "+f"((C)[2]), "+f"((C)[3]) \
        : "r"(A0), "r"(A1), "r"(A2), "r"(A3), "r"(B0), "r"(B1))

// ---------------- prep: pack codebooks (fp16 splits) + half-norms ----------------
__global__ void rvq_prep(const float* __restrict__ cb) {
    int e = blockIdx.x * blockDim.x + threadIdx.x;
    if (e >= LL * NEC) return;
    const float* row = cb + (size_t)e * DD;
    __half h[DD], lo[DD];
    float cn = 0.f;
    #pragma unroll
    for (int k = 0; k < DD; k++) {
        float v = row[k];
        sp16(v, h[k], lo[k]);
        cn = fmaf(v, v, cn);
    }
    g_cn[e] = 0.5f * cn;
    uint32_t* dst = g_bp + (size_t)e * 32;
    #pragma unroll
    for (int kk = 0; kk < 4; kk++) {
        dst[kk*4 + 0]      = packh2(h[2*kk],      h[2*kk + 1]);
        dst[kk*4 + 1]      = packh2(h[2*kk + 8],  h[2*kk + 9]);
        dst[kk*4 + 2]      = packh2(h[16 + 2*kk], h[16 + 2*kk + 1]);
        dst[kk*4 + 3]      = packh2(h[24 + 2*kk], h[24 + 2*kk + 1]);
        dst[16 + kk*4 + 0] = packh2(lo[2*kk],      lo[2*kk + 1]);
        dst[16 + kk*4 + 1] = packh2(lo[2*kk + 8],  lo[2*kk + 9]);
        dst[16 + kk*4 + 2] = packh2(lo[16 + 2*kk], lo[16 + 2*kk + 1]);
        dst[16 + kk*4 + 3] = packh2(lo[24 + 2*kk], lo[24 + 2*kk + 1]);
    }
}

// ---------------- main ----------------
__global__ void __launch_bounds__(TM, 4) rvq_mma_kernel(
    const float* __restrict__ x, const float* __restrict__ cb,
    float* __restrict__ out, int N, int has_loss, int has_idx, int nblk)
{
    extern __shared__ char smem[];
    const int tid = threadIdx.x;
    const int w = tid >> 5;
    const int lane = tid & 31;
    const int q = lane >> 2;       // MMA row group 0..7
    const int kk = lane & 3;       // thread-in-group
    const int p = blockIdx.x * TM + tid;
    const bool active = (p < N);

    char* rrow = smem + OFF_R + tid * 144;   // this thread's residual row (private)

    // init residual rows from x (inactive -> zeros)
    {
        float4* rp = (float4*)rrow;
        if (active) {
            const float4* xr = (const float4*)(x + (size_t)p * DD);
            #pragma unroll
            for (int j = 0; j < 8; j++) rp[j] = xr[j];
        } else {
            float4 z = make_float4(0.f, 0.f, 0.f, 0.f);
            #pragma unroll
            for (int j = 0; j < 8; j++) rp[j] = z;
        }
    }
    // stage all layers' cn (1024 floats)
    {
        float4* dst = (float4*)(smem + OFF_CN);
        #pragma unroll
        for (int i = tid; i < 256; i += TM) dst[i] = ((const float4*)g_cn)[i];
    }

    float tl[LL];
    int bia[LL];

    for (int l = 0; l < LL; l++) {
        __syncthreads();   // prior-layer B reads of SH done; cn staged (l=0)

        // ---- (a) write A = -residual fp16 splits into SH (144B/row) ----
        {
            float t[DD];
            const float4* rp = (const float4*)rrow;
            #pragma unroll
            for (int j = 0; j < 8; j++) {
                float4 v = rp[j];
                t[4*j] = v.x; t[4*j+1] = v.y; t[4*j+2] = v.z; t[4*j+3] = v.w;
            }
            char* ap = smem + OFF_SH + tid * 144;
            #pragma unroll
            for (int c4 = 0; c4 < 4; c4++) {
                __half h0,l0,h1,l1,h2,l2,h3,l3,h4,l4,h5,l5,h6,l6,h7,l7;
                sp16(-t[2*c4],        h0, l0); sp16(-t[2*c4 + 1],      h1, l1);
                sp16(-t[2*c4 + 8],    h2, l2); sp16(-t[2*c4 + 9],      h3, l3);
                sp16(-t[16 + 2*c4],   h4, l4); sp16(-t[16 + 2*c4 + 1], h5, l5);
                sp16(-t[24 + 2*c4],   h6, l6); sp16(-t[24 + 2*c4 + 1], h7, l7);
                uint4 Hw = make_uint4(packh2(h0,h1), packh2(h2,h3), packh2(h4,h5), packh2(h6,h7));
                uint4 Lw = make_uint4(packh2(l0,l1), packh2(l2,l3), packh2(l4,l5), packh2(l6,l7));
                *(uint4*)(ap + c4 * 16)      = Hw;
                *(uint4*)(ap + 64 + c4 * 16) = Lw;
            }
        }
        __syncthreads();

        // ---- (b) load A fragments (resident for the layer): 8 x LDS.128 ----
        uint4 U0h[2], U1h[2], U0l[2], U1l[2];
        {
            const char* ab = smem + OFF_SH + (size_t)(w * 32 + q) * 144 + kk * 16;
            #pragma unroll
            for (int m = 0; m < 2; m++) {
                U0h[m] = *(const uint4*)(ab + (m * 16) * 144);
                U1h[m] = *(const uint4*)(ab + (m * 16 + 8) * 144);
                U0l[m] = *(const uint4*)(ab + (m * 16) * 144 + 64);
                U1l[m] = *(const uint4*)(ab + (m * 16 + 8) * 144 + 64);
            }
        }
        __syncthreads();   // frags in regs; SH free for B

        float best[4];
        int bidx[4];
        #pragma unroll
        for (int j = 0; j < 4; j++) { best[j] = 3.402823466e38f; bidx[j] = 0; }

        #pragma unroll 1
        for (int chunk = 0; chunk < 2; chunk++) {
            // ---- stage B chunk: 128 codes x 128B payload -> 192B-stride smem ----
            {
                const uint4* src = (const uint4*)(g_bp + (size_t)(l * 256 + chunk * 128) * 32);
                #pragma unroll
                for (int i = tid; i < 1024; i += TM) {
                    int code = i >> 3, ch = i & 7;
                    *(uint4*)(smem + OFF_SH + code * 192 + ch * 16) = src[i];
                }
            }
            __syncthreads();

            const char* bb = smem + OFF_SH + q * 192 + kk * 16;
            const float2* cnp2 = (const float2*)(smem + OFF_CN + (l * 256 + chunk * 128 + kk * 2) * 4);

            #pragma unroll 4
            for (int nt = 0; nt < 16; nt++) {
                uint4 BH = *(const uint4*)(bb + nt * (8 * 192));
                uint4 BL = *(const uint4*)(bb + nt * (8 * 192) + 64);
                float2 cn = cnp2[nt * 4];   // floats at nt*8 offset

                float Ca[2][4], Cb[2][4];
                #pragma unroll
                for (int m = 0; m < 2; m++) {
                    Ca[m][0] = cn.x; Ca[m][1] = cn.y; Ca[m][2] = cn.x; Ca[m][3] = cn.y;
                    Cb[m][0] = 0.f;  Cb[m][1] = 0.f;  Cb[m][2] = 0.f;  Cb[m][3] = 0.f;
                }
                #pragma unroll
                for (int m = 0; m < 2; m++) {
                    MMA16(Ca[m], U0h[m].x, U1h[m].x, U0h[m].y, U1h[m].y, BH.x, BH.y); // h*h k0
                    MMA16(Ca[m], U0h[m].z, U1h[m].z, U0h[m].w, U1h[m].w, BH.z, BH.w); // h*h k1
                    MMA16(Cb[m], U0l[m].x, U1l[m].x, U0l[m].y, U1l[m].y, BH.x, BH.y); // l*h k0
                    MMA16(Cb[m], U0l[m].z, U1l[m].z, U0l[m].w, U1l[m].w, BH.z, BH.w); // l*h k1
                    MMA16(Cb[m], U0h[m].x, U1h[m].x, U0h[m].y, U1h[m].y, BL.x, BL.y); // h*l k0
                    MMA16(Cb[m], U0h[m].z, U1h[m].z, U0h[m].w, U1h[m].w, BL.z, BL.w); // h*l k1
                }

                int nb = chunk * 128 + nt * 8 + kk * 2;
                #pragma unroll
                for (int m = 0; m < 2; m++)
                    #pragma unroll
                    for (int hi = 0; hi < 2; hi++) {
                        float sc0 = Ca[m][hi*2]     + Cb[m][hi*2];
                        float sc1 = Ca[m][hi*2 + 1] + Cb[m][hi*2 + 1];
                        float mn = fminf(sc0, sc1);
                        int jj = m * 2 + hi;
                        if (mn < best[jj]) {          // rare; strict '<' keeps first idx
                            best[jj] = mn;
                            bidx[jj] = (sc1 < sc0) ? (nb + 1) : nb;
                        }
                    }
            }
            __syncthreads();   // all reads of this B chunk done before restage
        }

        // ---- argmin reduce across the 4 kk-lanes of each group ----
        #pragma unroll
        for (int jj = 0; jj < 4; jj++) {
            #pragma unroll
            for (int ofs = 1; ofs <= 2; ofs <<= 1) {
                float ob = __shfl_xor_sync(0xffffffffu, best[jj], ofs);
                int oi = __shfl_xor_sync(0xffffffffu, bidx[jj], ofs);
                if (ob < best[jj] || (ob == best[jj] && oi < bidx[jj])) {
                    best[jj] = ob; bidx[jj] = oi;
                }
            }
        }
        int* argb = (int*)(smem + OFF_ARG);
        if (kk == 0) {
            #pragma unroll
            for (int jj = 0; jj < 4; jj++)
                argb[w * 32 + (jj >> 1) * 16 + (jj & 1) * 8 + q] = bidx[jj];
        }
        __syncwarp();
        int bi = argb[w * 32 + lane];
        bia[l] = bi;

        // ---- residual update + loss (exact fp op sequence of the reference) ----
        {
            const float4* cg = (const float4*)(cb + ((size_t)l * NEC + bi) * DD);
            float4* rp = (float4*)rrow;
            float ls = 0.f;
            #pragma unroll
            for (int j = 0; j < 8; j++) {
                float4 c = cg[j];
                float4 rv = rp[j];
                float t0, xres;
                t0 = c.x - rv.x; ls = fmaf(t0, t0, ls); xres = rv.x + t0; rv.x = rv.x - xres;
                t0 = c.y - rv.y; ls = fmaf(t0, t0, ls); xres = rv.y + t0; rv.y = rv.y - xres;
                t0 = c.z - rv.z; ls = fmaf(t0, t0, ls); xres = rv.z + t0; rv.z = rv.z - xres;
                t0 = c.w - rv.w; ls = fmaf(t0, t0, ls); xres = rv.w + t0; rv.w = rv.w - xres;
                rp[j] = rv;
            }
            tl[l] = active ? ls : 0.f;
        }
    }

    // ---- outputs: x_q = x - r_final, indices ----
    if (active) {
        const float4* xr = (const float4*)(x + (size_t)p * DD);
        float4* qo = (float4*)(out + (size_t)p * DD);
        const float4* rp = (const float4*)rrow;
        #pragma unroll
        for (int j = 0; j < 8; j++) {
            float4 v = xr[j];
            float4 rv = rp[j];
            float4 qv;
            qv.x = v.x - rv.x; qv.y = v.y - rv.y;
            qv.z = v.z - rv.z; qv.w = v.w - rv.w;
            qo[j] = qv;
        }
        if (has_idx) {
            float* oi = out + (size_t)N * DD + (has_loss ? 1 : 0) + (size_t)p * LL;
            #pragma unroll
            for (int l = 0; l < LL; l++) oi[l] = (float)bia[l];
        }
    }

    // ---- per-block loss partials (deterministic tree) ----
    {
        float* red = (float*)(smem + OFF_RED);
        #pragma unroll
        for (int l = 0; l < LL; l++) {
            __syncthreads();
            red[tid] = tl[l];
            __syncthreads();
            #pragma unroll
            for (int s = TM / 2; s > 0; s >>= 1) {
                if (tid < s) red[tid] += red[tid + s];
                __syncthreads();
            }
            if (tid == 0) g_part[(size_t)blockIdx.x * LL + l] = red[0];
        }
    }

    // ---- last block finalizes loss (deterministic fixed-order), resets ctr ----
    __threadfence();
    unsigned* flag = (unsigned*)(smem + OFF_FLAG);
    if (tid == 0) {
        unsigned done = atomicAdd(&g_ctr, 1u);
        *flag = (done == (unsigned)(nblk - 1)) ? 1u : 0u;
    }
    __syncthreads();
    if (*flag) {
        __threadfence();
        double acc = 0.0;
        for (int b = tid; b < nblk; b += TM) {
            #pragma unroll
            for (int l = 0; l < LL; l++) acc += (double)g_part[(size_t)b * LL + l];
        }
        double* dred = (double*)(smem + OFF_RED);
        dred[tid] = acc;
        __syncthreads();
        #pragma unroll
        for (int s = TM / 2; s > 0; s >>= 1) {
            if (tid < s) dred[tid] += dred[tid + s];
            __syncthreads();
        }
        if (tid == 0) {
            if (has_loss) {
                double wgt = (1.0 + (double)RVQ_BETA) / ((double)N * (double)DD * (double)LL);
                out[(size_t)N * DD] = (float)(dred[0] * wgt);
            }
            g_ctr = 0u;
        }
    }
}

extern "C" void kernel_launch(void* const* d_in, const int* in_sizes, int n_in,
                              void* d_out, int out_size) {
    const float* x;
    const float* cb;
    int nx;
    if (n_in >= 2 && in_sizes[0] >= in_sizes[1]) {
        x = (const float*)d_in[0]; cb = (const float*)d_in[1]; nx = in_sizes[0];
    } else {
        x = (const float*)d_in[1]; cb = (const float*)d_in[0]; nx = in_sizes[1];
    }
    int N = nx / DD;
    float* out = (float*)d_out;

    long long need_full = (long long)N * DD + 1 + (long long)N * LL;
    int has_loss = (out_size > (long long)N * DD) ? 1 : 0;
    int has_idx  = (out_size >= need_full) ? 1 : 0;

    int nblk = (N + TM - 1) / TM;
    if (nblk > MAXBLK_P) nblk = MAXBLK_P;

    cudaFuncSetAttribute(rvq_mma_kernel, cudaFuncAttributeMaxDynamicSharedMemorySize, SMEM_BYTES);

    rvq_prep<<<(LL * NEC + 127) / 128, 128>>>(cb);
    rvq_mma_kernel<<<nblk, TM, SMEM_BYTES>>>(x, cb, out, N, has_loss, has_idx, nblk);
}